// round 5
// baseline (speedup 1.0000x reference)
#include <cuda_runtime.h>

#define EPSV 1e-7f
#define NPTS 131072
#define NT3  393216        // NPTS*3
#define NSEG 32

// ---- transposed-weight offsets (in floats) within d_wt ----
#define O_W1F 0
#define O_W1D 16384
#define O_W2F 32768
#define O_W2D 49152
#define O_W3  65536
#define O_WD1 81920
#define O_WR3 98304
#define O_W4F 114688
#define O_W4D 180224
#define O_W5  245760
#define O_WD2 311296
#define O_WR5 376832
#define WT_TOTAL 442368

// ---- static device scratch (no allocations allowed) ----
__device__ float d_wt[WT_TOTAL];
__device__ float d_g3s[128ull * (unsigned long long)NT3];   // vn3 output, layout [c][n*3+j]
__device__ float d_h5s[256ull * (unsigned long long)NT3];   // vn5 output, layout [c][n*3+j]
__device__ float d_r3[NSEG * 128 * 3];                      // relu3 output per segment
__device__ unsigned long long d_key1[NSEG * 128];
__device__ unsigned long long d_key2[NSEG * 256];

typedef unsigned long long u64;

// ---------------------------------------------------------------------------
// helpers
// ---------------------------------------------------------------------------
__device__ __forceinline__ u64 packkey(float dot, unsigned int n) {
    unsigned int u = __float_as_uint(dot);
    u = (u & 0x80000000u) ? ~u : (u | 0x80000000u);   // order-preserving float->uint
    return ((u64)u << 32) | (u64)(0xFFFFFFFFu - n);   // tie -> min n
}

__device__ __forceinline__ u64 shfl_xor_u64(u64 v, int m) {
    unsigned int lo = (unsigned int)v;
    unsigned int hi = (unsigned int)(v >> 32);
    lo = __shfl_xor_sync(0xFFFFFFFFu, lo, m);
    hi = __shfl_xor_sync(0xFFFFFFFFu, hi, m);
    return ((u64)hi << 32) | lo;
}

// packed fp32x2 FMA: d = a * b + d (lanewise, exact fp32 per lane)
__device__ __forceinline__ void ffma2(u64& d, u64 a, u64 b) {
    asm("fma.rn.f32x2 %0, %1, %2, %0;" : "+l"(d) : "l"(a), "l"(b));
}
__device__ __forceinline__ u64 packdup(float x) {
    u64 r;
    asm("mov.b64 %0, {%1, %1};" : "=l"(r) : "r"(__float_as_uint(x)));
    return r;
}
__device__ __forceinline__ void unpack2(u64 v, float& lo, float& hi) {
    unsigned int l, h;
    asm("mov.b64 {%0, %1}, %2;" : "=r"(l), "=r"(h) : "l"(v));
    lo = __uint_as_float(l);
    hi = __uint_as_float(h);
}

// cp.async 16B helpers
__device__ __forceinline__ void cpa16(float* smdst, const float4* gsrc) {
    unsigned s = (unsigned)__cvta_generic_to_shared(smdst);
    asm volatile("cp.async.cg.shared.global [%0], [%1], 16;" :: "r"(s), "l"(gsrc));
}
__device__ __forceinline__ void cp_commit() { asm volatile("cp.async.commit_group;"); }
__device__ __forceinline__ void cp_wait1() { asm volatile("cp.async.wait_group 1;" ::: "memory"); }
__device__ __forceinline__ void cp_wait0() { asm volatile("cp.async.wait_group 0;" ::: "memory"); }

// ---------------------------------------------------------------------------
// matmul cores. Thread tile: 8 output channels (4 packed pairs) x 3 components.
// wT k-major: wT[k*OTOT + o]. smW: double-buffered cp.async weight staging.
// ---------------------------------------------------------------------------
template<int K, int OTOT, int COLS, int KT, int NTH>
__device__ __forceinline__ void mm_pair2(const float* __restrict__ wfT, const float* __restrict__ wdT,
                                         const float* __restrict__ bufIn, float* smW,
                                         u64 accP[4][3], u64 accD[4][3],
                                         int o_base, int col_base, int tid)
{
    constexpr int TW    = KT * OTOT;
    constexpr int BUFSZ = 2 * TW;
    constexpr int NT    = K / KT;
    constexpr int PER   = TW / 4 / NTH;

    {
        float* df = smW;
        float* dd = smW + TW;
        const float4* sf = (const float4*)(wfT);
        const float4* sd = (const float4*)(wdT);
#pragma unroll
        for (int r = 0; r < PER; r++) {
            cpa16(df + (tid + NTH * r) * 4, sf + tid + NTH * r);
            cpa16(dd + (tid + NTH * r) * 4, sd + tid + NTH * r);
        }
        cp_commit();
    }
    for (int t = 0; t < NT; t++) {
        if (t + 1 < NT) {
            float* df = smW + ((t + 1) & 1) * BUFSZ;
            float* dd = df + TW;
            const float4* sf = (const float4*)(wfT + (t + 1) * KT * OTOT);
            const float4* sd = (const float4*)(wdT + (t + 1) * KT * OTOT);
#pragma unroll
            for (int r = 0; r < PER; r++) {
                cpa16(df + (tid + NTH * r) * 4, sf + tid + NTH * r);
                cpa16(dd + (tid + NTH * r) * 4, sd + tid + NTH * r);
            }
            cp_commit();
            cp_wait1();
        } else {
            cp_wait0();
        }
        __syncthreads();
        const float* Wf = smW + (t & 1) * BUFSZ;
        const float* Wd = Wf + TW;
#pragma unroll
        for (int kk = 0; kk < KT; kk++) {
            const ulonglong2* ar = (const ulonglong2*)(Wf + kk * OTOT + o_base);
            const ulonglong2* dr = (const ulonglong2*)(Wd + kk * OTOT + o_base);
            const float* br = bufIn + (t * KT + kk) * COLS + col_base;
            u64 B0 = packdup(br[0]);
            u64 B1 = packdup(br[1]);
            u64 B2 = packdup(br[2]);
            ulonglong2 af0 = ar[0], af1 = ar[1], ad0 = dr[0], ad1 = dr[1];
            u64 a2f[4] = {af0.x, af0.y, af1.x, af1.y};
            u64 a2d[4] = {ad0.x, ad0.y, ad1.x, ad1.y};
#pragma unroll
            for (int op = 0; op < 4; op++) {
                ffma2(accP[op][0], a2f[op], B0);
                ffma2(accP[op][1], a2f[op], B1);
                ffma2(accP[op][2], a2f[op], B2);
                ffma2(accD[op][0], a2d[op], B0);
                ffma2(accD[op][1], a2d[op], B1);
                ffma2(accD[op][2], a2d[op], B2);
            }
        }
        __syncthreads();
    }
}

template<int K, int OTOT, int COLS, int KT, int NTH>
__device__ __forceinline__ void mm_one2(const float* __restrict__ wT,
                                        const float* __restrict__ bufIn, float* smW,
                                        u64 acc[4][3], int o_base, int col_base, int tid)
{
    constexpr int TW  = KT * OTOT;
    constexpr int NT  = K / KT;
    constexpr int PER = TW / 4 / NTH;

    {
        const float4* sf = (const float4*)(wT);
#pragma unroll
        for (int r = 0; r < PER; r++)
            cpa16(smW + (tid + NTH * r) * 4, sf + tid + NTH * r);
        cp_commit();
    }
    for (int t = 0; t < NT; t++) {
        if (t + 1 < NT) {
            float* df = smW + ((t + 1) & 1) * TW;
            const float4* sf = (const float4*)(wT + (t + 1) * KT * OTOT);
#pragma unroll
            for (int r = 0; r < PER; r++)
                cpa16(df + (tid + NTH * r) * 4, sf + tid + NTH * r);
            cp_commit();
            cp_wait1();
        } else {
            cp_wait0();
        }
        __syncthreads();
        const float* Wf = smW + (t & 1) * TW;
#pragma unroll
        for (int kk = 0; kk < KT; kk++) {
            const ulonglong2* ar = (const ulonglong2*)(Wf + kk * OTOT + o_base);
            const float* br = bufIn + (t * KT + kk) * COLS + col_base;
            u64 B0 = packdup(br[0]);
            u64 B1 = packdup(br[1]);
            u64 B2 = packdup(br[2]);
            ulonglong2 af0 = ar[0], af1 = ar[1];
            u64 a2[4] = {af0.x, af0.y, af1.x, af1.y};
#pragma unroll
            for (int op = 0; op < 4; op++) {
                ffma2(acc[op][0], a2[op], B0);
                ffma2(acc[op][1], a2[op], B1);
                ffma2(acc[op][2], a2[op], B2);
            }
        }
        __syncthreads();
    }
}

__device__ __forceinline__ void zero_acc(u64 a[4][3]) {
#pragma unroll
    for (int op = 0; op < 4; op++)
#pragma unroll
        for (int cc = 0; cc < 3; cc++) a[op][cc] = 0ull;
}

__device__ __forceinline__ void unpack_acc(const u64 a[4][3], float f[8][3]) {
#pragma unroll
    for (int op = 0; op < 4; op++)
#pragma unroll
        for (int cc = 0; cc < 3; cc++)
            unpack2(a[op][cc], f[2 * op][cc], f[2 * op + 1][cc]);
}

// VN LeakyReLU (ns=0): one full 3-vector per channel per thread.
__device__ __forceinline__ void vn_combine(float fP[8][3], float fD[8][3])
{
#pragma unroll
    for (int oo = 0; oo < 8; oo++) {
        float p0 = fP[oo][0], p1 = fP[oo][1], p2 = fP[oo][2];
        float q0 = fD[oo][0], q1 = fD[oo][1], q2 = fD[oo][2];
        float dot = p0 * q0 + p1 * q1 + p2 * q2;
        float dn  = q0 * q0 + q1 * q1 + q2 * q2;
        if (dot < 0.f) {
            float s = dot / (dn + EPSV);
            fP[oo][0] = p0 - s * q0;
            fP[oo][1] = p1 - s * q1;
            fP[oo][2] = p2 - s * q2;
        }
    }
}

template<int COLS>
__device__ __forceinline__ void store_tile(float* buf, float f[8][3], int o_base, int col_base)
{
#pragma unroll
    for (int oo = 0; oo < 8; oo++) {
        float* r = buf + (o_base + oo) * COLS + col_base;
        r[0] = f[oo][0]; r[1] = f[oo][1]; r[2] = f[oo][2];
    }
}

// ---------------------------------------------------------------------------
// setup kernels
// ---------------------------------------------------------------------------
__global__ void k_initkeys()
{
    int i = blockIdx.x * blockDim.x + threadIdx.x;
    if (i < NSEG * 128) d_key1[i] = 0ull;
    if (i < NSEG * 256) d_key2[i] = 0ull;
}

struct TList {
    const float* src[7];
    int off[7];
};

// W[o][c] (OxC) -> d_wt[off + c*O + o]; one matrix per blockIdx.z
__global__ void k_tmany(TList tl, int O, int C)
{
    __shared__ float t[32][33];
    const float* src = tl.src[blockIdx.z];
    int dstOff = tl.off[blockIdx.z];
    int cb = blockIdx.x * 32, ob = blockIdx.y * 32;
    int x = threadIdx.x, y = threadIdx.y;
    for (int i = y; i < 32; i += 8) t[i][x] = src[(size_t)(ob + i) * C + cb + x];
    __syncthreads();
    for (int i = y; i < 32; i += 8) d_wt[dstOff + (size_t)(cb + i) * O + ob + x] = t[x][i];
}

// ---------------------------------------------------------------------------
// stage 1: vn1 -> vn2 -> vn3 -> (store g3, argmax over Wd1 dot)
// 32 points per CTA, 512 threads: ty=tid>>5 (o_base=ty*8), tx=tid&31 (point)
// smem: buf [128][96] (48KB, in-place) + smW 4*32*128 floats (64KB) = 112KB
// ---------------------------------------------------------------------------
__global__ void __launch_bounds__(512, 1) k_stage1(const float* __restrict__ x,
                                                   const int* __restrict__ radius)
{
    extern __shared__ float sm[];
    float* bufA = sm;                 // [128][96]
    float* smW  = sm + 12288;         // 4 x [32][128]
    int tid = threadIdx.x;
    int n0 = blockIdx.x * 32;

    // load X tile transposed: bufA[c][p*3+j] = x[n0+p][c][j]
    const float* xg = x + (size_t)n0 * 384;
    for (int i4 = tid; i4 < 3072; i4 += 512) {
        float4 v = ((const float4*)xg)[i4];
        int lin = i4 * 4;
        int p = lin / 384, r = lin % 384;
        float vv[4] = {v.x, v.y, v.z, v.w};
#pragma unroll
        for (int e = 0; e < 4; e++) {
            int rr = r + e;
            int c = rr / 3, j = rr - c * 3;
            bufA[c * 96 + p * 3 + j] = vv[e];
        }
    }

    int ty = tid >> 5, tx = tid & 31;
    int o_base = ty * 8, col_base = tx * 3;

    u64 aP[4][3], aD[4][3];
    float fP[8][3], fD[8][3];

    // L1: vn1
    zero_acc(aP); zero_acc(aD);
    mm_pair2<128, 128, 96, 32, 512>(d_wt + O_W1F, d_wt + O_W1D, bufA, smW, aP, aD, o_base, col_base, tid);
    unpack_acc(aP, fP); unpack_acc(aD, fD);
    vn_combine(fP, fD);
    store_tile<96>(bufA, fP, o_base, col_base);

    // L2: vn2
    zero_acc(aP); zero_acc(aD);
    mm_pair2<128, 128, 96, 32, 512>(d_wt + O_W2F, d_wt + O_W2D, bufA, smW, aP, aD, o_base, col_base, tid);
    unpack_acc(aP, fP); unpack_acc(aD, fD);
    vn_combine(fP, fD);
    store_tile<96>(bufA, fP, o_base, col_base);

    // L3: vn3
    zero_acc(aP);
    mm_one2<128, 128, 96, 32, 512>(d_wt + O_W3, bufA, smW, aP, o_base, col_base, tid);
    unpack_acc(aP, fP);
    store_tile<96>(bufA, fP, o_base, col_base);

    // write g3 to global scratch (layout [c][n*3+j])
#pragma unroll
    for (int oo = 0; oo < 8; oo++) {
        float* g = d_g3s + (size_t)(o_base + oo) * NT3 + (size_t)(n0 + tx) * 3;
        g[0] = fP[oo][0]; g[1] = fP[oo][1]; g[2] = fP[oo][2];
    }

    // L3d: d = Wd1 * Y   (bufA holds Y)
    zero_acc(aD);
    mm_one2<128, 128, 96, 32, 512>(d_wt + O_WD1, bufA, smW, aD, o_base, col_base, tid);
    unpack_acc(aD, fD);

    // per-(channel,point) dot, argmax reduce over the warp's 32 points
    int seg = radius[n0];
    unsigned int n = (unsigned int)(n0 + tx);
#pragma unroll
    for (int oo = 0; oo < 8; oo++) {
        float dot = fP[oo][0] * fD[oo][0] + fP[oo][1] * fD[oo][1] + fP[oo][2] * fD[oo][2];
        u64 best = packkey(dot, n);
#pragma unroll
        for (int m = 1; m < 32; m <<= 1) {
            u64 o = shfl_xor_u64(best, m);
            if (o > best) best = o;
        }
        if (tx == 0) atomicMax(&d_key1[seg * 128 + o_base + oo], best);
    }
}

// ---------------------------------------------------------------------------
// gather + relu3  (one block per segment, 128 threads)
// ---------------------------------------------------------------------------
__global__ void k_relu3()
{
    __shared__ float G[128][3];
    int seg = blockIdx.x, c = threadIdx.x;
    u64 key = d_key1[seg * 128 + c];
    unsigned int idx = 0xFFFFFFFFu - (unsigned int)(key & 0xFFFFFFFFull);
    if (idx >= NPTS) idx = 0;
    float g0 = d_g3s[(size_t)c * NT3 + (size_t)idx * 3 + 0];
    float g1 = d_g3s[(size_t)c * NT3 + (size_t)idx * 3 + 1];
    float g2 = d_g3s[(size_t)c * NT3 + (size_t)idx * 3 + 2];
    G[c][0] = g0; G[c][1] = g1; G[c][2] = g2;
    __syncthreads();
    float a0 = 0.f, a1 = 0.f, a2 = 0.f;
    const float* w = d_wt + O_WR3;   // k-major: w[k*128 + c]
    for (int k = 0; k < 128; k++) {
        float ww = w[k * 128 + c];
        a0 += ww * G[k][0]; a1 += ww * G[k][1]; a2 += ww * G[k][2];
    }
    float dot = g0 * a0 + g1 * a1 + g2 * a2;
    float dn  = a0 * a0 + a1 * a1 + a2 * a2;
    float o0 = g0, o1 = g1, o2 = g2;
    if (dot < 0.f) {
        float s = dot / (dn + EPSV);
        o0 -= s * a0; o1 -= s * a1; o2 -= s * a2;
    }
    d_r3[seg * 384 + c * 3 + 0] = o0;
    d_r3[seg * 384 + c * 3 + 1] = o1;
    d_r3[seg * 384 + c * 3 + 2] = o2;
}

// ---------------------------------------------------------------------------
// stage 2: concat -> vn4 -> vn5 -> (store h5, argmax over Wd2 dot)
// 16 points per CTA, 512 threads: ty=tid>>4 (o_base=ty*8), tx=tid&15 (point)
// smem: buf [256][48] (48KB, in-place) + smW 4*32*256 floats (128KB) = 176KB
// ---------------------------------------------------------------------------
__global__ void __launch_bounds__(512, 1) k_stage2(const float* __restrict__ x,
                                                   const int* __restrict__ radius)
{
    extern __shared__ float sm[];
    float* bufA = sm;                 // [256][48]
    float* smW  = sm + 12288;         // 4 x [32][256]
    int tid = threadIdx.x;
    int n0 = blockIdx.x * 16;
    int seg = radius[n0];

    // x part: bufA[c][p*3+j] = x[n0+p][c][j], c < 128
    const float* xg = x + (size_t)n0 * 384;
    for (int i4 = tid; i4 < 1536; i4 += 512) {
        float4 v = ((const float4*)xg)[i4];
        int lin = i4 * 4;
        int p = lin / 384, r = lin % 384;
        float vv[4] = {v.x, v.y, v.z, v.w};
#pragma unroll
        for (int e = 0; e < 4; e++) {
            int rr = r + e;
            int c = rr / 3, j = rr - c * 3;
            bufA[c * 48 + p * 3 + j] = vv[e];
        }
    }
    // r3 broadcast part: bufA[128+c][p*3+j] = r3[seg][c][j]
    const float* r3s = d_r3 + seg * 384;
    for (int i = tid; i < 128 * 48; i += 512) {
        int c = i / 48, col = i - c * 48;
        int j = col % 3;
        bufA[(128 + c) * 48 + col] = r3s[c * 3 + j];
    }

    int ty = tid >> 4, tx = tid & 15;
    int o_base = ty * 8, col_base = tx * 3;

    u64 aP[4][3], aD[4][3];
    float fP[8][3], fD[8][3];

    // L4: vn4
    zero_acc(aP); zero_acc(aD);
    mm_pair2<256, 256, 48, 32, 512>(d_wt + O_W4F, d_wt + O_W4D, bufA, smW, aP, aD, o_base, col_base, tid);
    unpack_acc(aP, fP); unpack_acc(aD, fD);
    vn_combine(fP, fD);
    store_tile<48>(bufA, fP, o_base, col_base);

    // L5: vn5
    zero_acc(aP);
    mm_one2<256, 256, 48, 32, 512>(d_wt + O_W5, bufA, smW, aP, o_base, col_base, tid);
    unpack_acc(aP, fP);
    store_tile<48>(bufA, fP, o_base, col_base);

    // write h5 scratch (layout [c][n*3+j])
#pragma unroll
    for (int oo = 0; oo < 8; oo++) {
        float* g = d_h5s + (size_t)(o_base + oo) * NT3 + (size_t)(n0 + tx) * 3;
        g[0] = fP[oo][0]; g[1] = fP[oo][1]; g[2] = fP[oo][2];
    }

    // L5d: d = Wd2 * Y   (bufA holds Y)
    zero_acc(aD);
    mm_one2<256, 256, 48, 32, 512>(d_wt + O_WD2, bufA, smW, aD, o_base, col_base, tid);
    unpack_acc(aD, fD);

    unsigned int n = (unsigned int)(n0 + tx);
#pragma unroll
    for (int oo = 0; oo < 8; oo++) {
        float dot = fP[oo][0] * fD[oo][0] + fP[oo][1] * fD[oo][1] + fP[oo][2] * fD[oo][2];
        u64 best = packkey(dot, n);
#pragma unroll
        for (int m = 1; m < 16; m <<= 1) {
            u64 o = shfl_xor_u64(best, m);
            if (o > best) best = o;
        }
        if (tx == 0) atomicMax(&d_key2[seg * 256 + o_base + oo], best);
    }
}

// ---------------------------------------------------------------------------
// gather + relu5 -> output  (one block per segment, 256 threads)
// ---------------------------------------------------------------------------
__global__ void k_relu5(float* __restrict__ out)
{
    __shared__ float G[256][3];
    int seg = blockIdx.x, c = threadIdx.x;
    u64 key = d_key2[seg * 256 + c];
    unsigned int idx = 0xFFFFFFFFu - (unsigned int)(key & 0xFFFFFFFFull);
    if (idx >= NPTS) idx = 0;
    float g0 = d_h5s[(size_t)c * NT3 + (size_t)idx * 3 + 0];
    float g1 = d_h5s[(size_t)c * NT3 + (size_t)idx * 3 + 1];
    float g2 = d_h5s[(size_t)c * NT3 + (size_t)idx * 3 + 2];
    G[c][0] = g0; G[c][1] = g1; G[c][2] = g2;
    __syncthreads();
    float a0 = 0.f, a1 = 0.f, a2 = 0.f;
    const float* w = d_wt + O_WR5;   // k-major: w[k*256 + c]
    for (int k = 0; k < 256; k++) {
        float ww = w[k * 256 + c];
        a0 += ww * G[k][0]; a1 += ww * G[k][1]; a2 += ww * G[k][2];
    }
    float dot = g0 * a0 + g1 * a1 + g2 * a2;
    float dn  = a0 * a0 + a1 * a1 + a2 * a2;
    float o0 = g0, o1 = g1, o2 = g2;
    if (dot < 0.f) {
        float s = dot / (dn + EPSV);
        o0 -= s * a0; o1 -= s * a1; o2 -= s * a2;
    }
    out[seg * 768 + c * 3 + 0] = o0;
    out[seg * 768 + c * 3 + 1] = o1;
    out[seg * 768 + c * 3 + 2] = o2;
}

// ---------------------------------------------------------------------------
// host launcher
// ---------------------------------------------------------------------------
extern "C" void kernel_launch(void* const* d_in, const int* in_sizes, int n_in,
                              void* d_out, int out_size)
{
    const float* x      = (const float*)d_in[0];
    const int*   radius = (const int*)d_in[1];

    cudaFuncSetAttribute(k_stage1, cudaFuncAttributeMaxDynamicSharedMemorySize, 114688);
    cudaFuncSetAttribute(k_stage2, cudaFuncAttributeMaxDynamicSharedMemorySize, 180224);

    k_initkeys<<<32, 256>>>();

    dim3 tb(32, 8);
    TList t128;
    t128.src[0] = (const float*)d_in[2];  t128.off[0] = O_W1F;
    t128.src[1] = (const float*)d_in[3];  t128.off[1] = O_W1D;
    t128.src[2] = (const float*)d_in[4];  t128.off[2] = O_W2F;
    t128.src[3] = (const float*)d_in[5];  t128.off[3] = O_W2D;
    t128.src[4] = (const float*)d_in[6];  t128.off[4] = O_W3;
    t128.src[5] = (const float*)d_in[7];  t128.off[5] = O_WD1;
    t128.src[6] = (const float*)d_in[8];  t128.off[6] = O_WR3;
    k_tmany<<<dim3(4, 4, 7), tb>>>(t128, 128, 128);

    TList t256;
    t256.src[0] = (const float*)d_in[9];   t256.off[0] = O_W4F;
    t256.src[1] = (const float*)d_in[10];  t256.off[1] = O_W4D;
    t256.src[2] = (const float*)d_in[11];  t256.off[2] = O_W5;
    t256.src[3] = (const float*)d_in[12];  t256.off[3] = O_WD2;
    t256.src[4] = (const float*)d_in[13];  t256.off[4] = O_WR5;
    t256.src[5] = t256.src[4];             t256.off[5] = O_WR5;  // unused (grid.z=5)
    t256.src[6] = t256.src[4];             t256.off[6] = O_WR5;
    k_tmany<<<dim3(8, 8, 5), tb>>>(t256, 256, 256);

    k_stage1<<<NPTS / 32, 512, 114688>>>(x, radius);
    k_relu3<<<NSEG, 128>>>();
    k_stage2<<<NPTS / 16, 512, 180224>>>(x, radius);
    k_relu5<<<NSEG, 256>>>((float*)d_out);
}